// round 8
// baseline (speedup 1.0000x reference)
#include <cuda_runtime.h>
#include <cstdint>

#define N_ATOMS 50000
#define M_NBR   12
#define N_ROWS  (N_ATOMS * M_NBR)
#define BN_EPS  1e-5f

// ---------------- scratch (device globals; no allocation) ----------------
__device__ float  g_P[(size_t)N_ATOMS * 512];       // [i][0:256)=atom@W1+bias, [256:512)=atom@W2
__device__ float  g_gated[(size_t)N_ROWS * 256];    // pre-BN gated features (active rows only)
__device__ float  g_nbrsum[(size_t)N_ATOMS * 128];
__device__ float  g_stats1[513];                    // S[256], SS[256], cnt
__device__ float  g_stats2[256];                    // S2[128], SS2[128]
__device__ int    g_rows[N_ROWS];                   // compacted active row indices
__device__ int    g_nactive;

#define SMEM_A_BYTES (49152)     // gemmA: s_a 32KB + s_w 16KB
#define SMEM_B_BYTES (51968)     // kernelB: s_v 16KB + s_w 32KB + meta 768B + s_st 1KB + pad

// ---------------- f32x2 helpers ----------------
__device__ __forceinline__ uint64_t dup2(float x) {
    uint64_t r; asm("mov.b64 %0, {%1, %1};" : "=l"(r) : "f"(x)); return r;
}
__device__ __forceinline__ void fma2(uint64_t& d, uint64_t a, uint64_t b) {
    asm("fma.rn.f32x2 %0, %1, %2, %0;" : "+l"(d) : "l"(a), "l"(b));
}
__device__ __forceinline__ float lo32(uint64_t v) { return __uint_as_float((unsigned)(v & 0xffffffffu)); }
__device__ __forceinline__ float hi32(uint64_t v) { return __uint_as_float((unsigned)(v >> 32)); }

__device__ __forceinline__ float sigmoid_fast(float x) {
    float z = __expf(-fabsf(x));
    return __fdividef((x >= 0.f) ? 1.f : z, 1.f + z);
}
__device__ __forceinline__ float softplus_fast(float x) {
    return fmaxf(x, 0.f) + __logf(1.f + __expf(-fabsf(x)));
}

// ---------------- kernel 0: zero stats ----------------
__global__ void zero_stats_kernel() {
    int t = threadIdx.x;
    if (t < 513) g_stats1[t] = 0.f;
    if (t < 256) g_stats2[t] = 0.f;
    if (t == 0)  g_nactive = 0;
}

// ---------------- kernel C: compact active rows ----------------
__global__ void compact_kernel(const float* __restrict__ mask) {
    int t = blockIdx.x * 256 + threadIdx.x;
    bool in = (t < N_ROWS) && (mask[t] != 0.f);
    unsigned b = __ballot_sync(0xffffffffu, in);
    int lane = threadIdx.x & 31;
    int cnt = __popc(b);
    int base = 0;
    if (lane == 0 && cnt) {
        base = atomicAdd(&g_nactive, cnt);
        atomicAdd(&g_stats1[512], (float)cnt);
    }
    base = __shfl_sync(0xffffffffu, base, 0);
    if (in) g_rows[base + __popc(b & ((1u << lane) - 1u))] = t;
}

// ---------------- kernel A: P = atom @ [W1|W2] + bias-fold ----
// Grid (782, 4): 64 rows x 128 cols per block; blockIdx.y = col-quarter of P[.,512].
// Thread: rows rg*8..rg*8+7, col quad 4cx. acc = 8x2 u64 (32 regs) -> 3 CTAs/SM.
// Inner k: 2 broadcast LDS.128 (A) + 8 reg-dups + 1 LDS.128 (W quad) + 16 fma2.
__global__ void __launch_bounds__(256, 3) gemmA_kernel(
    const float* __restrict__ atom, const float* __restrict__ W,
    const float* __restrict__ bias)
{
    extern __shared__ float smem[];
    float* s_a = smem;                 // [k][r] 128x64 (32KB)
    float* s_w = smem + 128 * 64;      // [kk][c] 32x128 (16KB)

    const int tid  = threadIdx.x;
    const int row0 = blockIdx.x * 64;
    const int h    = blockIdx.y;       // 0..3: P cols h*128 .. h*128+127

    const int rg = tid >> 5;           // rows rg*8 .. rg*8+7
    const int cx = tid & 31;           // local col quad 4cx

    const int wrow0 = (h < 2) ? 0 : 128;      // W1 vs W2 rows
    const int wcol0 = (h & 1) * 128;          // which 128-col slice

    // stage full A tile: 64 rows x 128 k, transposed
    for (int t = tid; t < 2048; t += 256) {
        int r  = t & 63;
        int kq = t >> 6;                           // 0..31
        float4 v = make_float4(0.f, 0.f, 0.f, 0.f);
        int gr = row0 + r;
        if (gr < N_ATOMS) v = *(const float4*)(atom + (size_t)gr * 128 + kq * 4);
        s_a[(kq * 4 + 0) * 64 + r] = v.x;
        s_a[(kq * 4 + 1) * 64 + r] = v.y;
        s_a[(kq * 4 + 2) * 64 + r] = v.z;
        s_a[(kq * 4 + 3) * 64 + r] = v.w;
    }

    uint64_t acc[8][2];
    #pragma unroll
    for (int r = 0; r < 8; r++) { acc[r][0] = 0ull; acc[r][1] = 0ull; }

    for (int chunk = 0; chunk < 4; chunk++) {
        const int k0 = chunk * 32;
        __syncthreads();
        for (int t = tid; t < 1024; t += 256) {    // 32 k x 128 c
            int kk = t >> 5;
            int c4 = (t & 31) * 4;
            *(float4*)(s_w + kk * 128 + c4) =
                *(const float4*)(W + (size_t)(wrow0 + k0 + kk) * 256 + wcol0 + c4);
        }
        __syncthreads();

        #pragma unroll 4
        for (int kk = 0; kk < 32; kk++) {
            const float* sa = s_a + (k0 + kk) * 64 + rg * 8;
            float4 a03 = *(const float4*)(sa);
            float4 a47 = *(const float4*)(sa + 4);
            uint64_t ad[8] = { dup2(a03.x), dup2(a03.y), dup2(a03.z), dup2(a03.w),
                               dup2(a47.x), dup2(a47.y), dup2(a47.z), dup2(a47.w) };
            ulonglong2 w01 = *(const ulonglong2*)(s_w + kk * 128 + 4 * cx);
            #pragma unroll
            for (int r = 0; r < 8; r++) {
                fma2(acc[r][0], ad[r], w01.x);
                fma2(acc[r][1], ad[r], w01.y);
            }
        }
    }

    // epilogue: float4 stores, bias folded only for P cols < 256 (h<2)
    float4 ba = make_float4(0.f, 0.f, 0.f, 0.f);
    if (h < 2) ba = *(const float4*)(bias + h * 128 + 4 * cx);

    #pragma unroll
    for (int r = 0; r < 8; r++) {
        int row = row0 + rg * 8 + r;
        if (row >= N_ATOMS) break;
        float4 va = make_float4(lo32(acc[r][0]) + ba.x, hi32(acc[r][0]) + ba.y,
                                lo32(acc[r][1]) + ba.z, hi32(acc[r][1]) + ba.w);
        *(float4*)(g_P + (size_t)row * 512 + h * 128 + 4 * cx) = va;
    }
}

// ---------------- kernel B: gated = nbr@W3 + P1(+b) + P2[idx] (active rows) ----
// Grid (ceil(rows/64), 2): 64 compacted rows x 128 cols; ch = col-half.
// W3 half (64k x 128c, 32KB) staged once; acc = 8x2 u64 -> 3 CTAs/SM.
__global__ void __launch_bounds__(256, 3) kernelB(
    const float* __restrict__ nbr, const int* __restrict__ idx,
    const float* __restrict__ W)
{
    extern __shared__ float smem[];
    float* s_v   = smem;                        // [k][r] 64x64 (16KB)
    float* s_w   = smem + 64 * 64;              // [k][c] 64x128 (32KB)
    int*   s_row = (int*)(s_w + 64 * 128);      // 64
    int*   s_atom= s_row + 64;
    int*   s_idx = s_atom + 64;
    float* s_st  = (float*)(s_idx + 64);        // 256: S[128], SS[128] (local cols)

    const int na    = g_nactive;
    const int slot0 = blockIdx.x * 64;
    if (slot0 >= na) return;

    const int tid = threadIdx.x;
    const int ch  = blockIdx.y;                 // col-half: global cols ch*128 + lc

    if (tid < 64) {
        int slot = slot0 + tid;
        int gr = (slot < na) ? g_rows[slot] : -1;
        s_row[tid]  = gr;
        s_atom[tid] = (gr >= 0) ? (gr / 12) : 0;
        s_idx[tid]  = (gr >= 0) ? idx[gr] : 0;
    }
    s_st[tid] = 0.f;
    __syncthreads();

    // stage V: 64 rows x 64 k (transposed)
    for (int t = tid; t < 1024; t += 256) {
        int r  = t & 63;
        int kq = t >> 6;                 // 0..15
        int gr = s_row[r];
        float4 v = make_float4(0.f, 0.f, 0.f, 0.f);
        if (gr >= 0) v = *(const float4*)(nbr + (size_t)gr * 64 + kq * 4);
        s_v[(kq * 4 + 0) * 64 + r] = v.x;
        s_v[(kq * 4 + 1) * 64 + r] = v.y;
        s_v[(kq * 4 + 2) * 64 + r] = v.z;
        s_v[(kq * 4 + 3) * 64 + r] = v.w;
    }
    // stage W3 half: 64 k x 128 c
    for (int t = tid; t < 2048; t += 256) {
        int k  = t >> 5;
        int c4 = (t & 31) * 4;
        *(float4*)(s_w + k * 128 + c4) =
            *(const float4*)(W + (size_t)(256 + k) * 256 + ch * 128 + c4);
    }
    __syncthreads();

    const int rg = tid >> 5;
    const int cx = tid & 31;             // local col quad 4cx

    uint64_t acc[8][2];
    #pragma unroll
    for (int r = 0; r < 8; r++) { acc[r][0] = 0ull; acc[r][1] = 0ull; }

    #pragma unroll 4
    for (int k = 0; k < 64; k++) {
        const float* sv = s_v + k * 64 + rg * 8;
        float4 a03 = *(const float4*)(sv);
        float4 a47 = *(const float4*)(sv + 4);
        uint64_t ad[8] = { dup2(a03.x), dup2(a03.y), dup2(a03.z), dup2(a03.w),
                           dup2(a47.x), dup2(a47.y), dup2(a47.z), dup2(a47.w) };
        ulonglong2 w01 = *(const ulonglong2*)(s_w + k * 128 + 4 * cx);
        #pragma unroll
        for (int r = 0; r < 8; r++) {
            fma2(acc[r][0], ad[r], w01.x);
            fma2(acc[r][1], ad[r], w01.y);
        }
    }

    // epilogue: add P1(+bias) + P2[idx], float4 stores, per-col stats
    float sq[4] = {0,0,0,0}, ss[4] = {0,0,0,0};

    #pragma unroll
    for (int r = 0; r < 8; r++) {
        int rr   = rg * 8 + r;
        int slot = slot0 + rr;
        if (slot >= na) break;
        int gr = s_row[rr];
        const float* P1 = g_P + (size_t)s_atom[rr] * 512 + ch * 128;
        const float* P2 = g_P + (size_t)s_idx[rr] * 512 + 256 + ch * 128;
        float4 p1 = *(const float4*)(P1 + 4 * cx);
        float4 p2 = *(const float4*)(P2 + 4 * cx);
        float4 va = make_float4(lo32(acc[r][0]) + p1.x + p2.x,
                                hi32(acc[r][0]) + p1.y + p2.y,
                                lo32(acc[r][1]) + p1.z + p2.z,
                                hi32(acc[r][1]) + p1.w + p2.w);
        *(float4*)(g_gated + (size_t)gr * 256 + ch * 128 + 4 * cx) = va;
        sq[0] += va.x; sq[1] += va.y; sq[2] += va.z; sq[3] += va.w;
        ss[0] = fmaf(va.x, va.x, ss[0]); ss[1] = fmaf(va.y, va.y, ss[1]);
        ss[2] = fmaf(va.z, va.z, ss[2]); ss[3] = fmaf(va.w, va.w, ss[3]);
    }
    #pragma unroll
    for (int t = 0; t < 4; t++) {
        atomicAdd(&s_st[4 * cx + t],       sq[t]);
        atomicAdd(&s_st[128 + 4 * cx + t], ss[t]);
    }
    __syncthreads();
    if (tid < 128) atomicAdd(&g_stats1[ch * 128 + tid], s_st[tid]);
    else           atomicAdd(&g_stats1[256 + ch * 128 + (tid - 128)], s_st[tid]);
}

// ---------------- kernel D: BN1 + sigmoid*softplus + sum_j, + BN2 stats ----
// 16 atoms per block, 256 threads: lane=channel pair (float2), grp=atom group.
__global__ void __launch_bounds__(256) kernelD(
    const float* __restrict__ mask,
    const float* __restrict__ gamma1, const float* __restrict__ beta1)
{
    __shared__ float s2[256];

    const int tid   = threadIdx.x;
    const int lane  = tid & 63;          // channel pair c = 2*lane (0..126)
    const int grp   = tid >> 6;          // 0..3
    const int atom0 = blockIdx.x * 16;

    s2[tid] = 0.f;

    const int c = 2 * lane;
    const float inv_cnt = __fdividef(1.f, g_stats1[512]);
    float2 Sf  = *(const float2*)(g_stats1 + c);
    float2 Sc  = *(const float2*)(g_stats1 + 128 + c);
    float2 SSf = *(const float2*)(g_stats1 + 256 + c);
    float2 SSc = *(const float2*)(g_stats1 + 256 + 128 + c);
    float2 gf  = *(const float2*)(gamma1 + c);
    float2 gc  = *(const float2*)(gamma1 + 128 + c);
    float2 bf  = *(const float2*)(beta1 + c);
    float2 bcr = *(const float2*)(beta1 + 128 + c);

    float2 mf = make_float2(Sf.x * inv_cnt, Sf.y * inv_cnt);
    float2 mc = make_float2(Sc.x * inv_cnt, Sc.y * inv_cnt);
    float2 sf = make_float2(rsqrtf(SSf.x * inv_cnt - mf.x * mf.x + BN_EPS) * gf.x,
                            rsqrtf(SSf.y * inv_cnt - mf.y * mf.y + BN_EPS) * gf.y);
    float2 sc = make_float2(rsqrtf(SSc.x * inv_cnt - mc.x * mc.x + BN_EPS) * gc.x,
                            rsqrtf(SSc.y * inv_cnt - mc.y * mc.y + BN_EPS) * gc.y);
    __syncthreads();

    float2 sloc = make_float2(0.f, 0.f), ssloc = make_float2(0.f, 0.f);

    #pragma unroll
    for (int a = 0; a < 4; a++) {
        const int i = atom0 + grp * 4 + a;
        float m[12];
        #pragma unroll
        for (int j = 0; j < 12; j++) m[j] = __ldg(mask + i * 12 + j);

        float2 accv = make_float2(0.f, 0.f);
        #pragma unroll
        for (int half = 0; half < 2; half++) {
            float2 vf[6], vc[6];
            #pragma unroll
            for (int j = 0; j < 6; j++) {
                int jj = half * 6 + j;
                const float* gp = g_gated + (size_t)(i * 12 + jj) * 256;
                bool act = (m[jj] != 0.f);
                vf[j] = act ? *(const float2*)(gp + c)       : make_float2(0.f, 0.f);
                vc[j] = act ? *(const float2*)(gp + 128 + c) : make_float2(0.f, 0.f);
            }
            #pragma unroll
            for (int j = 0; j < 6; j++) {
                int jj = half * 6 + j;
                if (m[jj] != 0.f) {
                    float hfx = (vf[j].x - mf.x) * sf.x + bf.x;
                    float hfy = (vf[j].y - mf.y) * sf.y + bf.y;
                    float hcx = (vc[j].x - mc.x) * sc.x + bcr.x;
                    float hcy = (vc[j].y - mc.y) * sc.y + bcr.y;
                    accv.x += sigmoid_fast(hfx) * softplus_fast(hcx);
                    accv.y += sigmoid_fast(hfy) * softplus_fast(hcy);
                }
            }
        }
        *(float2*)(g_nbrsum + (size_t)i * 128 + c) = accv;
        sloc.x  += accv.x;               sloc.y  += accv.y;
        ssloc.x  = fmaf(accv.x, accv.x, ssloc.x);
        ssloc.y  = fmaf(accv.y, accv.y, ssloc.y);
    }
    atomicAdd(&s2[c],           sloc.x);
    atomicAdd(&s2[c + 1],       sloc.y);
    atomicAdd(&s2[128 + c],     ssloc.x);
    atomicAdd(&s2[128 + c + 1], ssloc.y);
    __syncthreads();
    atomicAdd(&g_stats2[tid], s2[tid]);
}

// ---------------- kernel F: out = softplus(atom + BN2(nbrsum)) ----------------
__global__ void __launch_bounds__(256) kernelF(
    const float* __restrict__ atom,
    const float* __restrict__ gamma2, const float* __restrict__ beta2,
    float* __restrict__ out)
{
    int t = blockIdx.x * 256 + threadIdx.x;
    if (t >= N_ATOMS * 128) return;
    int c = t & 127;
    const float invN = 1.f / (float)N_ATOMS;
    float mean = g_stats2[c] * invN;
    float var  = g_stats2[128 + c] * invN - mean * mean;
    float x = (g_nbrsum[t] - mean) * rsqrtf(var + BN_EPS) * gamma2[c] + beta2[c];
    out[t] = softplus_fast(atom[t] + x);
}

// ---------------- launch ----------------
extern "C" void kernel_launch(void* const* d_in, const int* in_sizes, int n_in,
                              void* d_out, int out_size)
{
    const float* atom   = (const float*)d_in[0];
    const float* nbr    = (const float*)d_in[1];
    const int*   idx    = (const int*)  d_in[2];
    const float* mask   = (const float*)d_in[3];
    const float* W      = (const float*)d_in[4];
    const float* bias   = (const float*)d_in[5];
    const float* gamma1 = (const float*)d_in[6];
    const float* beta1  = (const float*)d_in[7];
    const float* gamma2 = (const float*)d_in[8];
    const float* beta2  = (const float*)d_in[9];
    float* out = (float*)d_out;

    cudaFuncSetAttribute(gemmA_kernel, cudaFuncAttributeMaxDynamicSharedMemorySize, SMEM_A_BYTES);
    cudaFuncSetAttribute(kernelB,      cudaFuncAttributeMaxDynamicSharedMemorySize, SMEM_B_BYTES);

    zero_stats_kernel<<<1, 1024>>>();
    compact_kernel<<<(N_ROWS + 255) / 256, 256>>>(mask);
    gemmA_kernel<<<dim3((N_ATOMS + 63) / 64, 4), 256, SMEM_A_BYTES>>>(atom, W, bias);
    kernelB<<<dim3((N_ROWS + 63) / 64, 2), 256, SMEM_B_BYTES>>>(nbr, idx, W);
    kernelD<<<N_ATOMS / 16, 256>>>(mask, gamma1, beta1);
    kernelF<<<(N_ATOMS * 128) / 256, 256>>>(atom, gamma2, beta2, out);
}

// round 11
// speedup vs baseline: 1.0608x; 1.0608x over previous
#include <cuda_runtime.h>
#include <cstdint>

#define N_ATOMS 50000
#define M_NBR   12
#define N_ROWS  (N_ATOMS * M_NBR)
#define BN_EPS  1e-5f
#define NB_B    304              // persistent kernelB blocks: 152 SMs x 2 CTAs

// ---------------- scratch (device globals; no allocation) ----------------
__device__ float  g_P[(size_t)N_ATOMS * 512];       // [i][0:256)=atom@W1+bias, [256:512)=atom@W2
__device__ float  g_gated[(size_t)N_ROWS * 256];    // pre-BN gated features (active rows only)
__device__ float  g_nbrsum[(size_t)N_ATOMS * 128];
__device__ float  g_stats1[513];                    // S[256], SS[256], cnt
__device__ float  g_stats2[256];                    // S2[128], SS2[128]
__device__ int    g_rows[N_ROWS];                   // compacted active row indices
__device__ int    g_nactive;

#define SMEM_A_BYTES (65536)     // gemmA: s_a 32KB + s_w 32KB
#define SMEM_B_BYTES (101888)    // kernelB: W3 64KB + 2x V 16KB + meta 1.5KB + stats 2KB

// ---------------- f32x2 helpers ----------------
__device__ __forceinline__ uint64_t dup2(float x) {
    uint64_t r; asm("mov.b64 %0, {%1, %1};" : "=l"(r) : "f"(x)); return r;
}
__device__ __forceinline__ void fma2(uint64_t& d, uint64_t a, uint64_t b) {
    asm("fma.rn.f32x2 %0, %1, %2, %0;" : "+l"(d) : "l"(a), "l"(b));
}
__device__ __forceinline__ float lo32(uint64_t v) { return __uint_as_float((unsigned)(v & 0xffffffffu)); }
__device__ __forceinline__ float hi32(uint64_t v) { return __uint_as_float((unsigned)(v >> 32)); }

__device__ __forceinline__ float sigmoid_fast(float x) {
    float z = __expf(-fabsf(x));
    return __fdividef((x >= 0.f) ? 1.f : z, 1.f + z);
}
__device__ __forceinline__ float softplus_fast(float x) {
    return fmaxf(x, 0.f) + __logf(1.f + __expf(-fabsf(x)));
}

// ---------------- kernel 0: zero stats ----------------
__global__ void zero_stats_kernel() {
    int t = threadIdx.x;
    if (t < 513) g_stats1[t] = 0.f;
    if (t < 256) g_stats2[t] = 0.f;
    if (t == 0)  g_nactive = 0;
}

// ---------------- kernel C: compact active rows ----------------
__global__ void compact_kernel(const float* __restrict__ mask) {
    int t = blockIdx.x * 256 + threadIdx.x;
    bool in = (t < N_ROWS) && (mask[t] != 0.f);
    unsigned b = __ballot_sync(0xffffffffu, in);
    int lane = threadIdx.x & 31;
    int cnt = __popc(b);
    int base = 0;
    if (lane == 0 && cnt) {
        base = atomicAdd(&g_nactive, cnt);
        atomicAdd(&g_stats1[512], (float)cnt);
    }
    base = __shfl_sync(0xffffffffu, base, 0);
    if (in) g_rows[base + __popc(b & ((1u << lane) - 1u))] = t;
}

// ---------------- kernel A: P = atom @ [W1|W2] + bias-fold (R7 shape) ----
// Grid (782, 2): 64 rows x 256 cols per block; blockIdx.y selects W1/W2.
// Thread: rows rg*8..rg*8+7, col-quads 4cx+128q (q=0..1). A staged once.
__global__ void __launch_bounds__(256, 2) gemmA_kernel(
    const float* __restrict__ atom, const float* __restrict__ W,
    const float* __restrict__ bias)
{
    extern __shared__ float smem[];
    float* s_a = smem;                 // [k][r] 128x64 (32KB)
    float* s_w = smem + 128 * 64;      // [kk][c] 32x256 (32KB)

    const int tid  = threadIdx.x;
    const int row0 = blockIdx.x * 64;
    const int h    = blockIdx.y;

    const int rg = tid >> 5;
    const int cx = tid & 31;

    for (int t = tid; t < 2048; t += 256) {
        int r  = t & 63;
        int kq = t >> 6;
        float4 v = make_float4(0.f, 0.f, 0.f, 0.f);
        int gr = row0 + r;
        if (gr < N_ATOMS) v = *(const float4*)(atom + (size_t)gr * 128 + kq * 4);
        s_a[(kq * 4 + 0) * 64 + r] = v.x;
        s_a[(kq * 4 + 1) * 64 + r] = v.y;
        s_a[(kq * 4 + 2) * 64 + r] = v.z;
        s_a[(kq * 4 + 3) * 64 + r] = v.w;
    }

    uint64_t acc[8][4];
    #pragma unroll
    for (int r = 0; r < 8; r++)
        #pragma unroll
        for (int j = 0; j < 4; j++) acc[r][j] = 0ull;

    for (int chunk = 0; chunk < 4; chunk++) {
        const int k0 = chunk * 32;
        __syncthreads();
        for (int t = tid; t < 2048; t += 256) {
            int kk = t >> 6;
            int c4 = (t & 63) * 4;
            *(float4*)(s_w + kk * 256 + c4) =
                *(const float4*)(W + (size_t)(h * 128 + k0 + kk) * 256 + c4);
        }
        __syncthreads();

        #pragma unroll 4
        for (int kk = 0; kk < 32; kk++) {
            const float* sa = s_a + (k0 + kk) * 64 + rg * 8;
            float4 a03 = *(const float4*)(sa);
            float4 a47 = *(const float4*)(sa + 4);
            uint64_t ad[8] = { dup2(a03.x), dup2(a03.y), dup2(a03.z), dup2(a03.w),
                               dup2(a47.x), dup2(a47.y), dup2(a47.z), dup2(a47.w) };
            ulonglong2 w01 = *(const ulonglong2*)(s_w + kk * 256 + 4 * cx);
            ulonglong2 w23 = *(const ulonglong2*)(s_w + kk * 256 + 4 * cx + 128);
            uint64_t wp[4] = { w01.x, w01.y, w23.x, w23.y };
            #pragma unroll
            for (int r = 0; r < 8; r++)
                #pragma unroll
                for (int j = 0; j < 4; j++)
                    fma2(acc[r][j], ad[r], wp[j]);
        }
    }

    float4 ba = make_float4(0.f, 0.f, 0.f, 0.f), bb = ba;
    if (h == 0) {
        ba = *(const float4*)(bias + 4 * cx);
        bb = *(const float4*)(bias + 4 * cx + 128);
    }

    #pragma unroll
    for (int r = 0; r < 8; r++) {
        int row = row0 + rg * 8 + r;
        if (row >= N_ATOMS) break;
        float* dst = g_P + (size_t)row * 512 + h * 256;
        float4 va = make_float4(lo32(acc[r][0]) + ba.x, hi32(acc[r][0]) + ba.y,
                                lo32(acc[r][1]) + ba.z, hi32(acc[r][1]) + ba.w);
        float4 vb = make_float4(lo32(acc[r][2]) + bb.x, hi32(acc[r][2]) + bb.y,
                                lo32(acc[r][3]) + bb.z, hi32(acc[r][3]) + bb.w);
        *(float4*)(dst + 4 * cx)       = va;
        *(float4*)(dst + 4 * cx + 128) = vb;
    }
}

// ---------------- kernel B (PERSISTENT): gated = nbr@W3 + P1(+b) + P2[idx] ----
// 304 blocks, each: stage W3 (64KB) once; loop 64-row tiles with double-buffered
// V tile (prefetch next V into regs during mainloop); one sync per tile;
// BN1 stats accumulated in smem, flushed once.
__global__ void __launch_bounds__(256, 2) kernelB(
    const float* __restrict__ nbr, const int* __restrict__ idx,
    const float* __restrict__ W)
{
    extern __shared__ float smem[];
    float* s_w  = smem;                          // [k][c] 64x256 (64KB)
    float* s_vb = smem + 64 * 256;               // 2 x [k][r] 64x64 (2x16KB)
    int*   s_mt = (int*)(s_vb + 2 * 64 * 64);    // 2 x {row[64], atom[64], idx[64]}
    float* s_st = (float*)(s_mt + 2 * 192);      // S[256], SS[256]

    const int tid = threadIdx.x;
    const int na  = g_nactive;
    const int rg  = tid >> 5;
    const int cx  = tid & 31;

    // stage full W3 once
    for (int t = tid; t < 4096; t += 256) {
        int k  = t >> 6;
        int c4 = (t & 63) * 4;
        *(float4*)(s_w + k * 256 + c4) =
            *(const float4*)(W + (size_t)(256 + k) * 256 + c4);
    }
    s_st[tid] = 0.f;
    s_st[tid + 256] = 0.f;

    // prologue: stage meta + V for first tile into buffer 0
    int tile = blockIdx.x;
    if (tile * 64 < na) {
        int slot0 = tile * 64;
        if (tid < 64) {
            int slot = slot0 + tid;
            int gr = (slot < na) ? g_rows[slot] : -1;
            s_mt[tid]       = gr;
            s_mt[64 + tid]  = (gr >= 0) ? (gr / 12) : 0;
            s_mt[128 + tid] = (gr >= 0) ? idx[gr] : 0;
        }
        #pragma unroll
        for (int j = 0; j < 4; j++) {
            int tt = tid + 256 * j;
            int r = tt & 63, kq = tt >> 6;
            int slot = slot0 + r;
            int gr = (slot < na) ? g_rows[slot] : -1;
            float4 v = make_float4(0.f, 0.f, 0.f, 0.f);
            if (gr >= 0) v = *(const float4*)(nbr + (size_t)gr * 64 + kq * 4);
            s_vb[(kq * 4 + 0) * 64 + r] = v.x;
            s_vb[(kq * 4 + 1) * 64 + r] = v.y;
            s_vb[(kq * 4 + 2) * 64 + r] = v.z;
            s_vb[(kq * 4 + 3) * 64 + r] = v.w;
        }
    }
    __syncthreads();

    int buf = 0;
    for (; tile * 64 < na; tile += NB_B) {
        const int  ntile   = tile + NB_B;
        const bool hasnext = (ntile * 64 < na);

        // prefetch next tile: meta -> spare smem bank, V -> registers
        float4 pv0, pv1, pv2, pv3;
        if (hasnext) {
            int slot0n = ntile * 64;
            if (tid < 64) {
                int slot = slot0n + tid;
                int gr = (slot < na) ? g_rows[slot] : -1;
                int* mt = s_mt + (buf ^ 1) * 192;
                mt[tid]       = gr;
                mt[64 + tid]  = (gr >= 0) ? (gr / 12) : 0;
                mt[128 + tid] = (gr >= 0) ? idx[gr] : 0;
            }
            #pragma unroll
            for (int j = 0; j < 4; j++) {
                int tt = tid + 256 * j;
                int r = tt & 63, kq = tt >> 6;
                int slot = slot0n + r;
                int gr = (slot < na) ? g_rows[slot] : -1;
                float4 v = make_float4(0.f, 0.f, 0.f, 0.f);
                if (gr >= 0) v = *(const float4*)(nbr + (size_t)gr * 64 + kq * 4);
                if (j == 0) pv0 = v; else if (j == 1) pv1 = v;
                else if (j == 2) pv2 = v; else pv3 = v;
            }
        }

        // mainloop on current buffer
        const float* sv = s_vb + buf * 4096;
        uint64_t acc[8][4];
        #pragma unroll
        for (int r = 0; r < 8; r++)
            #pragma unroll
            for (int j = 0; j < 4; j++) acc[r][j] = 0ull;

        #pragma unroll 4
        for (int k = 0; k < 64; k++) {
            const float* svk = sv + k * 64 + rg * 8;
            float4 a03 = *(const float4*)(svk);
            float4 a47 = *(const float4*)(svk + 4);
            uint64_t ad[8] = { dup2(a03.x), dup2(a03.y), dup2(a03.z), dup2(a03.w),
                               dup2(a47.x), dup2(a47.y), dup2(a47.z), dup2(a47.w) };
            ulonglong2 w01 = *(const ulonglong2*)(s_w + k * 256 + 4 * cx);
            ulonglong2 w23 = *(const ulonglong2*)(s_w + k * 256 + 4 * cx + 128);
            uint64_t wp[4] = { w01.x, w01.y, w23.x, w23.y };
            #pragma unroll
            for (int r = 0; r < 8; r++)
                #pragma unroll
                for (int j = 0; j < 4; j++)
                    fma2(acc[r][j], ad[r], wp[j]);
        }

        // store prefetched V into spare buffer
        if (hasnext) {
            float* dv = s_vb + (buf ^ 1) * 4096;
            #pragma unroll
            for (int j = 0; j < 4; j++) {
                int tt = tid + 256 * j;
                int r = tt & 63, kq = tt >> 6;
                float4 v = (j == 0) ? pv0 : (j == 1) ? pv1 : (j == 2) ? pv2 : pv3;
                dv[(kq * 4 + 0) * 64 + r] = v.x;
                dv[(kq * 4 + 1) * 64 + r] = v.y;
                dv[(kq * 4 + 2) * 64 + r] = v.z;
                dv[(kq * 4 + 3) * 64 + r] = v.w;
            }
        }

        // epilogue: add P1(+bias) + P2[idx], float4 stores, smem stats
        const int* mt    = s_mt + buf * 192;
        const int  slot0 = tile * 64;
        float sqa[4] = {0,0,0,0}, sqb[4] = {0,0,0,0};
        float ssa[4] = {0,0,0,0}, ssb[4] = {0,0,0,0};

        #pragma unroll
        for (int r = 0; r < 8; r++) {
            int rr   = rg * 8 + r;
            int slot = slot0 + rr;
            if (slot >= na) break;
            int gr = mt[rr];
            const float* P1 = g_P + (size_t)mt[64 + rr] * 512;
            const float* P2 = g_P + (size_t)mt[128 + rr] * 512 + 256;
            float4 p1a = *(const float4*)(P1 + 4 * cx);
            float4 p1b = *(const float4*)(P1 + 4 * cx + 128);
            float4 p2a = *(const float4*)(P2 + 4 * cx);
            float4 p2b = *(const float4*)(P2 + 4 * cx + 128);
            float4 va = make_float4(lo32(acc[r][0]) + p1a.x + p2a.x,
                                    hi32(acc[r][0]) + p1a.y + p2a.y,
                                    lo32(acc[r][1]) + p1a.z + p2a.z,
                                    hi32(acc[r][1]) + p1a.w + p2a.w);
            float4 vb = make_float4(lo32(acc[r][2]) + p1b.x + p2b.x,
                                    hi32(acc[r][2]) + p1b.y + p2b.y,
                                    lo32(acc[r][3]) + p1b.z + p2b.z,
                                    hi32(acc[r][3]) + p1b.w + p2b.w);
            float* Gout = g_gated + (size_t)gr * 256;
            *(float4*)(Gout + 4 * cx)       = va;
            *(float4*)(Gout + 4 * cx + 128) = vb;
            sqa[0] += va.x; sqa[1] += va.y; sqa[2] += va.z; sqa[3] += va.w;
            sqb[0] += vb.x; sqb[1] += vb.y; sqb[2] += vb.z; sqb[3] += vb.w;
            ssa[0] = fmaf(va.x, va.x, ssa[0]); ssa[1] = fmaf(va.y, va.y, ssa[1]);
            ssa[2] = fmaf(va.z, va.z, ssa[2]); ssa[3] = fmaf(va.w, va.w, ssa[3]);
            ssb[0] = fmaf(vb.x, vb.x, ssb[0]); ssb[1] = fmaf(vb.y, vb.y, ssb[1]);
            ssb[2] = fmaf(vb.z, vb.z, ssb[2]); ssb[3] = fmaf(vb.w, vb.w, ssb[3]);
        }
        #pragma unroll
        for (int t = 0; t < 4; t++) {
            atomicAdd(&s_st[4 * cx + t],             sqa[t]);
            atomicAdd(&s_st[4 * cx + 128 + t],       sqb[t]);
            atomicAdd(&s_st[256 + 4 * cx + t],       ssa[t]);
            atomicAdd(&s_st[256 + 4 * cx + 128 + t], ssb[t]);
        }
        __syncthreads();
        buf ^= 1;
    }

    // flush stats once per block
    atomicAdd(&g_stats1[tid],       s_st[tid]);
    atomicAdd(&g_stats1[256 + tid], s_st[256 + tid]);
}

// ---------------- kernel D: BN1 + sigmoid*softplus + sum_j, + BN2 stats ----
__global__ void __launch_bounds__(256) kernelD(
    const float* __restrict__ mask,
    const float* __restrict__ gamma1, const float* __restrict__ beta1)
{
    __shared__ float s2[256];

    const int tid   = threadIdx.x;
    const int lane  = tid & 63;
    const int grp   = tid >> 6;
    const int atom0 = blockIdx.x * 16;

    s2[tid] = 0.f;

    const int c = 2 * lane;
    const float inv_cnt = __fdividef(1.f, g_stats1[512]);
    float2 Sf  = *(const float2*)(g_stats1 + c);
    float2 Sc  = *(const float2*)(g_stats1 + 128 + c);
    float2 SSf = *(const float2*)(g_stats1 + 256 + c);
    float2 SSc = *(const float2*)(g_stats1 + 256 + 128 + c);
    float2 gf  = *(const float2*)(gamma1 + c);
    float2 gc  = *(const float2*)(gamma1 + 128 + c);
    float2 bf  = *(const float2*)(beta1 + c);
    float2 bcr = *(const float2*)(beta1 + 128 + c);

    float2 mf = make_float2(Sf.x * inv_cnt, Sf.y * inv_cnt);
    float2 mc = make_float2(Sc.x * inv_cnt, Sc.y * inv_cnt);
    float2 sf = make_float2(rsqrtf(SSf.x * inv_cnt - mf.x * mf.x + BN_EPS) * gf.x,
                            rsqrtf(SSf.y * inv_cnt - mf.y * mf.y + BN_EPS) * gf.y);
    float2 sc = make_float2(rsqrtf(SSc.x * inv_cnt - mc.x * mc.x + BN_EPS) * gc.x,
                            rsqrtf(SSc.y * inv_cnt - mc.y * mc.y + BN_EPS) * gc.y);
    __syncthreads();

    float2 sloc = make_float2(0.f, 0.f), ssloc = make_float2(0.f, 0.f);

    #pragma unroll
    for (int a = 0; a < 4; a++) {
        const int i = atom0 + grp * 4 + a;
        float m[12];
        #pragma unroll
        for (int j = 0; j < 12; j++) m[j] = __ldg(mask + i * 12 + j);

        float2 accv = make_float2(0.f, 0.f);
        #pragma unroll
        for (int half = 0; half < 2; half++) {
            float2 vf[6], vc[6];
            #pragma unroll
            for (int j = 0; j < 6; j++) {
                int jj = half * 6 + j;
                const float* gp = g_gated + (size_t)(i * 12 + jj) * 256;
                bool act = (m[jj] != 0.f);
                vf[j] = act ? *(const float2*)(gp + c)       : make_float2(0.f, 0.f);
                vc[j] = act ? *(const float2*)(gp + 128 + c) : make_float2(0.f, 0.f);
            }
            #pragma unroll
            for (int j = 0; j < 6; j++) {
                int jj = half * 6 + j;
                if (m[jj] != 0.f) {
                    float hfx = (vf[j].x - mf.x) * sf.x + bf.x;
                    float hfy = (vf[j].y - mf.y) * sf.y + bf.y;
                    float hcx = (vc[j].x - mc.x) * sc.x + bcr.x;
                    float hcy = (vc[j].y - mc.y) * sc.y + bcr.y;
                    accv.x += sigmoid_fast(hfx) * softplus_fast(hcx);
                    accv.y += sigmoid_fast(hfy) * softplus_fast(hcy);
                }
            }
        }
        *(float2*)(g_nbrsum + (size_t)i * 128 + c) = accv;
        sloc.x  += accv.x;               sloc.y  += accv.y;
        ssloc.x  = fmaf(accv.x, accv.x, ssloc.x);
        ssloc.y  = fmaf(accv.y, accv.y, ssloc.y);
    }
    atomicAdd(&s2[c],           sloc.x);
    atomicAdd(&s2[c + 1],       sloc.y);
    atomicAdd(&s2[128 + c],     ssloc.x);
    atomicAdd(&s2[128 + c + 1], ssloc.y);
    __syncthreads();
    atomicAdd(&g_stats2[tid], s2[tid]);
}

// ---------------- kernel F: out = softplus(atom + BN2(nbrsum)) ----------------
__global__ void __launch_bounds__(256) kernelF(
    const float* __restrict__ atom,
    const float* __restrict__ gamma2, const float* __restrict__ beta2,
    float* __restrict__ out)
{
    int t = blockIdx.x * 256 + threadIdx.x;
    if (t >= N_ATOMS * 128) return;
    int c = t & 127;
    const float invN = 1.f / (float)N_ATOMS;
    float mean = g_stats2[c] * invN;
    float var  = g_stats2[128 + c] * invN - mean * mean;
    float x = (g_nbrsum[t] - mean) * rsqrtf(var + BN_EPS) * gamma2[c] + beta2[c];
    out[t] = softplus_fast(atom[t] + x);
}

// ---------------- launch ----------------
extern "C" void kernel_launch(void* const* d_in, const int* in_sizes, int n_in,
                              void* d_out, int out_size)
{
    const float* atom   = (const float*)d_in[0];
    const float* nbr    = (const float*)d_in[1];
    const int*   idx    = (const int*)  d_in[2];
    const float* mask   = (const float*)d_in[3];
    const float* W      = (const float*)d_in[4];
    const float* bias   = (const float*)d_in[5];
    const float* gamma1 = (const float*)d_in[6];
    const float* beta1  = (const float*)d_in[7];
    const float* gamma2 = (const float*)d_in[8];
    const float* beta2  = (const float*)d_in[9];
    float* out = (float*)d_out;

    cudaFuncSetAttribute(gemmA_kernel, cudaFuncAttributeMaxDynamicSharedMemorySize, SMEM_A_BYTES);
    cudaFuncSetAttribute(kernelB,      cudaFuncAttributeMaxDynamicSharedMemorySize, SMEM_B_BYTES);

    zero_stats_kernel<<<1, 1024>>>();
    compact_kernel<<<(N_ROWS + 255) / 256, 256>>>(mask);
    gemmA_kernel<<<dim3((N_ATOMS + 63) / 64, 2), 256, SMEM_A_BYTES>>>(atom, W, bias);
    kernelB<<<NB_B, 256, SMEM_B_BYTES>>>(nbr, idx, W);
    kernelD<<<N_ATOMS / 16, 256>>>(mask, gamma1, beta1);
    kernelF<<<(N_ATOMS * 128) / 256, 256>>>(atom, gamma2, beta2, out);
}